// round 8
// baseline (speedup 1.0000x reference)
#include <cuda_runtime.h>
#include <cuda_bf16.h>
#include <math.h>
#include <stdint.h>

#define BATCH 8
#define NPTS  500
#define MHYP  144

// table offsets (floats): L0: 8*48*64=24576 ; L1: +8*96*128 -> 122880 ; total +8*192*256
#define TAB_TOTAL 516096

__device__ float g_tabS [TAB_TOTAL];
__device__ float g_tabCh[TAB_TOTAL];
__device__ float g_tabCv[TAB_TOTAL];
__device__ float g_tabCd[TAB_TOTAL];
__device__ float g_tabCa[TAB_TOTAL];
__device__ float g_Tcur [BATCH * MHYP * 16];
__device__ float g_costs[BATCH * MHYP];
__device__ float g_tnoise[MHYP * 3];
__device__ float g_noise [9 * BATCH * MHYP * 6];

// ---------------- JAX threefry2x32 (bit-exact) ----------------
__device__ __forceinline__ void threefry2x32(uint32_t k0, uint32_t k1,
                                             uint32_t c0, uint32_t c1,
                                             uint32_t& o0, uint32_t& o1)
{
    uint32_t ks0 = k0, ks1 = k1, ks2 = k0 ^ k1 ^ 0x1BD11BDAu;
    uint32_t x0 = c0 + ks0;
    uint32_t x1 = c1 + ks1;
#define TF_ROT(v,d) (((v) << (d)) | ((v) >> (32 - (d))))
#define TF_R(r) { x0 += x1; x1 = TF_ROT(x1, r); x1 ^= x0; }
    TF_R(13) TF_R(15) TF_R(26) TF_R(6)   x0 += ks1; x1 += ks2 + 1u;
    TF_R(17) TF_R(29) TF_R(16) TF_R(24)  x0 += ks2; x1 += ks0 + 2u;
    TF_R(13) TF_R(15) TF_R(26) TF_R(6)   x0 += ks0; x1 += ks1 + 3u;
    TF_R(17) TF_R(29) TF_R(16) TF_R(24)  x0 += ks1; x1 += ks2 + 4u;
    TF_R(13) TF_R(15) TF_R(26) TF_R(6)   x0 += ks2; x1 += ks0 + 5u;
#undef TF_R
#undef TF_ROT
    o0 = x0; o1 = x1;
}

// Partitionable threefry random_bits (modern JAX default):
// element i -> counter (0, i), 32-bit output = o0 ^ o1.
__device__ __forceinline__ uint32_t tf_bits_partitionable(uint32_t k0, uint32_t k1,
                                                          uint32_t i)
{
    uint32_t o0, o1;
    threefry2x32(k0, k1, 0u, i, o0, o1);
    return o0 ^ o1;
}

__device__ __forceinline__ float bits_to_normal(uint32_t bits)
{
    float f  = __uint_as_float((bits >> 9) | 0x3F800000u) - 1.0f;
    float lo = __uint_as_float(0xBF7FFFFFu); // nextafter(-1, 0)
    float u  = fmaxf(lo, f * 2.0f + lo);     // (hi-lo) rounds to 2.0f; f*2 exact
    return 1.41421356237309515f * erfinvf(u);
}

// ---------------- SE(3) helpers ----------------
__device__ __forceinline__ void se3_exp(const float xi[6], float T[16])
{
    float wx = xi[3], wy = xi[4], wz = xi[5];
    float nw = sqrtf(wx*wx + wy*wy + wz*wz);
    float theta = fmaxf(nw, 1e-8f);
    float inv = 1.0f / theta;
    float ux = wx * inv, uy = wy * inv, uz = wz * inv;
    float K[9] = {0.f, -uz, uy,  uz, 0.f, -ux,  -uy, ux, 0.f};
    float KK[9];
#pragma unroll
    for (int r = 0; r < 3; r++)
#pragma unroll
        for (int c = 0; c < 3; c++)
            KK[r*3+c] = K[r*3+0]*K[0*3+c] + K[r*3+1]*K[1*3+c] + K[r*3+2]*K[2*3+c];
    float st = sinf(theta);
    float ct = 1.0f - cosf(theta);
    float cth = ct * inv;
    float sth = 1.0f - st * inv;
    float R[9], V[9];
#pragma unroll
    for (int k = 0; k < 9; k++) {
        float eye = (k == 0 || k == 4 || k == 8) ? 1.0f : 0.0f;
        R[k] = eye + st  * K[k] + ct  * KK[k];
        V[k] = eye + cth * K[k] + sth * KK[k];
    }
    float t0 = V[0]*xi[0] + V[1]*xi[1] + V[2]*xi[2];
    float t1 = V[3]*xi[0] + V[4]*xi[1] + V[5]*xi[2];
    float t2 = V[6]*xi[0] + V[7]*xi[1] + V[8]*xi[2];
    T[0]=R[0]; T[1]=R[1]; T[2]=R[2];  T[3]=t0;
    T[4]=R[3]; T[5]=R[4]; T[6]=R[5];  T[7]=t1;
    T[8]=R[6]; T[9]=R[7]; T[10]=R[8]; T[11]=t2;
    T[12]=0.f; T[13]=0.f; T[14]=0.f;  T[15]=1.f;
}

__device__ __forceinline__ void mat4_mul(const float* A, const float* B, float* C)
{
#pragma unroll
    for (int r = 0; r < 4; r++)
#pragma unroll
        for (int c = 0; c < 4; c++)
            C[r*4+c] = A[r*4+0]*B[0*4+c] + A[r*4+1]*B[1*4+c]
                     + A[r*4+2]*B[2*4+c] + A[r*4+3]*B[3*4+c];
}

__device__ __forceinline__ float geod_norm(const float T[16])
{
    float tr = T[0] + T[5] + T[10];
    float ca = (tr - 1.0f) * 0.5f;
    ca = fminf(fmaxf(ca, -1.0f + 1e-7f), 1.0f - 1e-7f);
    float theta = acosf(ca);
    float th = fmaxf(theta, 1e-8f);
    float s  = fmaxf(sinf(th), 1e-8f);
    float k  = th / (2.0f * s);
    float wx = (T[9] - T[6]) * k;
    float wy = (T[2] - T[8]) * k;
    float wz = (T[4] - T[1]) * k;
    if (fabsf(theta) < 1e-6f) { wx = 0.f; wy = 0.f; wz = 0.f; }
    float tx = T[3], ty = T[7], tz = T[11];
    return sqrtf(tx*tx + ty*ty + tz*tz + wx*wx + wy*wy + wz*wz);
}

// ---------------- Kernel 1: all PRNG draws (partitionable threefry) ----------------
// grid (28,10) x 256. y=0 -> t_noise (432 vals), y=1..9 -> iter noise (6912 vals)
__global__ void noise_kernel()
{
    int i = blockIdx.x * blockDim.x + threadIdx.x;
    int j = blockIdx.y;
    if (j == 0) {
        if (i >= 432) return;
        uint32_t hk0, hk1;
        threefry2x32(0u, 42u, 0u, 0u, hk0, hk1);            // fold_in(key(42), 0)
        g_tnoise[i] = bits_to_normal(tf_bits_partitionable(hk0, hk1, (uint32_t)i));
    } else {
        int it = j - 1;
        if (i >= 6912) return;
        int level = (it < 2) ? 0 : ((it < 5) ? 1 : 2);
        int li = it - ((level == 0) ? 0 : ((level == 1) ? 2 : 5));
        uint32_t data = (uint32_t)(100 + level * 10 + li);
        uint32_t hk0, hk1;
        threefry2x32(0u, 42u, 0u, data, hk0, hk1);          // fold_in(key(42), data)
        g_noise[it * 6912 + i] =
            bits_to_normal(tf_bits_partitionable(hk0, hk1, (uint32_t)i));
    }
}

// ---------------- Kernel 2: hypotheses + cost init ----------------
__global__ void hyp_kernel(const float* __restrict__ Tpred)
{
    int t = blockIdx.x * blockDim.x + threadIdx.x;
    if (t >= BATCH * MHYP) return;
    int b = t / MHYP, m = t - b * MHYP;
    g_costs[t] = 0.0f;
    const float D2R = 0.017453292519943295f;
    float pitch = (-11.0f + 2.0f * (float)(m / 12)) * D2R;
    float yaw   = (-11.0f + 2.0f * (float)(m % 12)) * D2R;
    float xi[6] = { g_tnoise[m*3+0], g_tnoise[m*3+1], g_tnoise[m*3+2],
                    0.0f, pitch, yaw };
    float dT[16]; se3_exp(xi, dT);
    float Tn[16]; mat4_mul(dT, Tpred + b * 16, Tn);
#pragma unroll
    for (int k = 0; k < 16; k++) g_Tcur[t * 16 + k] = Tn[k];
}

// ---------------- Kernel 3: neighbor Gram tables of D = q - r ----------------
// S  = <D(x,y),D(x,y)>   Ch = <D(x,y),D(xp,y)>   Cv = <D(x,y),D(x,yp)>
// Cd = <D(x,y),D(xp,yp)> Ca = <D(xp,y),D(x,yp)>   xp=min(x+1,W-1), yp=min(y+1,H-1)
// grid (ceil(W/31), H, B), block 256, dyn smem 2*32*(C+4) floats
__global__ __launch_bounds__(256)
void gram_kernel(const float* __restrict__ q, const float* __restrict__ r,
                 int C, int H, int W, int tab_off)
{
    extern __shared__ float sD[]; // [2][32][C+4]
    const int pitchC = C + 4;
    const int b = blockIdx.z, y = blockIdx.y;
    const int x0t = blockIdx.x * 31;
    const int yd = min(y + 1, H - 1);
    const int tid = threadIdx.x;

    const int half = C << 5;
    const int total = half * 2;
    for (int e = tid; e < total; e += 256) {
        int row = (e >= half) ? 1 : 0;
        int rem = e - row * half;
        int c  = rem >> 5;
        int px = rem & 31;
        int gx = min(x0t + px, W - 1);
        int gy = row ? yd : y;
        int gi = ((b * C + c) * H + gy) * W + gx;
        sD[(row * 32 + px) * pitchC + c] = q[gi] - r[gi];
    }
    __syncthreads();

    const int lane = tid & 31, warp = tid >> 5;
    const int LPP = C >> 2;        // lanes per pixel
    const int PPW = 32 / LPP;      // pixels per warp
    const int px_sub = lane / LPP;
    const int cl = lane - px_sub * LPP;
    const int c4 = cl * 4;

    for (int base = warp * PPW; base < 31; base += 8 * PPW) {
        int px  = base + px_sub;
        int pxc = min(px, 30);
        const float4 a  = *(const float4*)&sD[(pxc)          * pitchC + c4];
        const float4 bb = *(const float4*)&sD[(pxc + 1)      * pitchC + c4];
        const float4 cc = *(const float4*)&sD[(32 + pxc)     * pitchC + c4];
        const float4 dd = *(const float4*)&sD[(32 + pxc + 1) * pitchC + c4];
        float vS = a.x*a.x  + a.y*a.y  + a.z*a.z  + a.w*a.w;
        float vH = a.x*bb.x + a.y*bb.y + a.z*bb.z + a.w*bb.w;
        float vV = a.x*cc.x + a.y*cc.y + a.z*cc.z + a.w*cc.w;
        float vD = a.x*dd.x + a.y*dd.y + a.z*dd.z + a.w*dd.w;
        float vA = bb.x*cc.x + bb.y*cc.y + bb.z*cc.z + bb.w*cc.w;
        for (int off = LPP >> 1; off > 0; off >>= 1) {
            vS += __shfl_xor_sync(0xFFFFFFFFu, vS, off);
            vH += __shfl_xor_sync(0xFFFFFFFFu, vH, off);
            vV += __shfl_xor_sync(0xFFFFFFFFu, vV, off);
            vD += __shfl_xor_sync(0xFFFFFFFFu, vD, off);
            vA += __shfl_xor_sync(0xFFFFFFFFu, vA, off);
        }
        int x = x0t + px;
        if (cl == 0 && px < 31 && x < W) {
            int o = tab_off + (b * H + y) * W + x;
            g_tabS [o] = vS;
            g_tabCh[o] = vH;
            g_tabCv[o] = vV;
            g_tabCd[o] = vD;
            g_tabCa[o] = vA;
        }
    }
}

// ---------------- Kernel 4: one LM iteration ----------------
// block = (b*16 + m), 256 threads: residual over 500 points + pose update
__global__ __launch_bounds__(256)
void iter_kernel(const float* __restrict__ geo,
                 const float* __restrict__ Kin,
                 const float* __restrict__ unc,
                 int H, int W, int tab_off, float scale,
                 int noise_idx, float damping)
{
    const int b = blockIdx.x >> 4;
    const int m = blockIdx.x & 15;
    const int tid = threadIdx.x;
    __shared__ float sT[16];
    __shared__ float sred[8];
    if (tid < 16) sT[tid] = g_Tcur[(b * MHYP + m) * 16 + tid];
    __syncthreads();

    const float fx = Kin[b*9+0] * scale, cx = Kin[b*9+2] * scale;
    const float fy = Kin[b*9+4] * scale, cy = Kin[b*9+5] * scale;
    const float* U = unc + b * H * W;
    const int tb = tab_off + b * H * W;
    const float Wm1 = (float)(W - 1), Hm1 = (float)(H - 1);
    const float Wf = (float)W, Hf = (float)H;

    float local = 0.0f;
    for (int n = tid; n < NPTS; n += 256) {
        float X = geo[(b*NPTS + n)*3 + 0];
        float Y = geo[(b*NPTS + n)*3 + 1];
        float Z = geo[(b*NPTS + n)*3 + 2];
        float pc0 = sT[0]*X + sT[1]*Y + sT[2]*Z  + sT[3];
        float pc1 = sT[4]*X + sT[5]*Y + sT[6]*Z  + sT[7];
        float pc2 = sT[8]*X + sT[9]*Y + sT[10]*Z + sT[11];
        float z = fmaxf(pc2, 1e-6f);
        float uu = fx * (pc0 / z) + cx;
        float vv = fy * (pc1 / z) + cy;
        float gx = 2.0f * uu / Wm1 - 1.0f;
        float gy = 2.0f * vv / Hm1 - 1.0f;
        float x = fminf(fmaxf(((gx + 1.0f) * Wf - 1.0f) * 0.5f, 0.0f), Wm1);
        float y = fminf(fmaxf(((gy + 1.0f) * Hf - 1.0f) * 0.5f, 0.0f), Hm1);
        float x0f = floorf(x), y0f = floorf(y);
        float wx = x - x0f, wy = y - y0f;
        int x0 = (int)x0f, y0 = (int)y0f;
        int x1 = min(x0 + 1, W - 1), y1 = min(y0 + 1, H - 1);
        float ox = 1.0f - wx, oy = 1.0f - wy;
        float w00 = ox*oy, wX0 = wx*oy, w0Y = ox*wy, wXY = wx*wy;
        int i00 = tb + y0*W + x0;
        int i10 = tb + y0*W + x1;
        int i01 = tb + y1*W + x0;
        int i11 = tb + y1*W + x1;
        float S00 = __ldg(&g_tabS[i00]);
        float S10 = __ldg(&g_tabS[i10]);
        float S01 = __ldg(&g_tabS[i01]);
        float S11 = __ldg(&g_tabS[i11]);
        float ChA = __ldg(&g_tabCh[i00]);
        float ChB = __ldg(&g_tabCh[i01]);
        float CvA = __ldg(&g_tabCv[i00]);
        float CvB = __ldg(&g_tabCv[i10]);
        float CdA = __ldg(&g_tabCd[i00]);
        float CaA = __ldg(&g_tabCa[i00]);
        float quad = w00*w00*S00 + wX0*wX0*S10 + w0Y*w0Y*S01 + wXY*wXY*S11
                   + 2.0f*(w00*wX0*ChA + w0Y*wXY*ChB + w00*w0Y*CvA
                         + wX0*wXY*CvB + w00*wXY*CdA + wX0*w0Y*CaA);
        float us = __ldg(&U[y0*W + x0]) * w00 + __ldg(&U[y0*W + x1]) * wX0
                 + __ldg(&U[y1*W + x0]) * w0Y + __ldg(&U[y1*W + x1]) * wXY;
        local += quad * us;
    }
#pragma unroll
    for (int off = 16; off > 0; off >>= 1)
        local += __shfl_xor_sync(0xFFFFFFFFu, local, off);
    if ((tid & 31) == 0) sred[tid >> 5] = local;
    __syncthreads();
    if (tid == 0) {
        float s = 0.0f;
#pragma unroll
        for (int w = 0; w < 8; w++) s += sred[w];
        float res = s / (float)NPTS;
        g_costs[b * MHYP + m] = res;
        float a1 = -damping * res;
        const float* nz = g_noise + noise_idx * 6912 + (b * MHYP + m) * 6;
        float xi[6];
#pragma unroll
        for (int k = 0; k < 6; k++) xi[k] = a1 * nz[k] * 0.01f;
        float dT[16]; se3_exp(xi, dT);
        float Tn[16]; mat4_mul(dT, sT, Tn);
#pragma unroll
        for (int k = 0; k < 16; k++) g_Tcur[(b * MHYP + m) * 16 + k] = Tn[k];
    }
}

// ---------------- Kernel 5: finalize (geodesic + argmin + outputs) ----------------
__global__ void final_kernel(const float* __restrict__ Tpred, float* __restrict__ out)
{
    int b = blockIdx.x;
    int t = threadIdx.x; // 160 threads
    __shared__ float sInv[16];
    __shared__ float sTot[MHYP];
    __shared__ int sBest;
    if (t == 0) {
        const float* Tp = Tpred + b * 16;
        sInv[0]=Tp[0]; sInv[1]=Tp[4]; sInv[2] =Tp[8];
        sInv[4]=Tp[1]; sInv[5]=Tp[5]; sInv[6] =Tp[9];
        sInv[8]=Tp[2]; sInv[9]=Tp[6]; sInv[10]=Tp[10];
        sInv[3]  = -(Tp[0]*Tp[3] + Tp[4]*Tp[7] + Tp[8]*Tp[11]);
        sInv[7]  = -(Tp[1]*Tp[3] + Tp[5]*Tp[7] + Tp[9]*Tp[11]);
        sInv[11] = -(Tp[2]*Tp[3] + Tp[6]*Tp[7] + Tp[10]*Tp[11]);
        sInv[12]=0.f; sInv[13]=0.f; sInv[14]=0.f; sInv[15]=1.f;
    }
    __syncthreads();
    if (t < MHYP) {
        float Trel[16];
        mat4_mul(&g_Tcur[(b * MHYP + t) * 16], sInv, Trel);
        float c = g_costs[b * MHYP + t];
        sTot[t] = c + geod_norm(Trel);
        out[BATCH * 16 + b * MHYP + t] = c;
    }
    __syncthreads();
    if (t == 0) {
        float best = sTot[0]; int bi = 0;
        for (int mm = 1; mm < MHYP; mm++)
            if (sTot[mm] < best) { best = sTot[mm]; bi = mm; }
        sBest = bi;
    }
    __syncthreads();
    if (t < 16) out[b * 16 + t] = g_Tcur[(b * MHYP + sBest) * 16 + t];
}

// ---------------- launch ----------------
extern "C" void kernel_launch(void* const* d_in, const int* in_sizes, int n_in,
                              void* d_out, int out_size)
{
    const float* Tpred = (const float*)d_in[0];
    const float* geo   = (const float*)d_in[1];
    const float* Kin   = (const float*)d_in[2];
    const float* q[3]  = {(const float*)d_in[3], (const float*)d_in[4], (const float*)d_in[5]};
    const float* r[3]  = {(const float*)d_in[6], (const float*)d_in[7], (const float*)d_in[8]};
    const float* u[3]  = {(const float*)d_in[9], (const float*)d_in[10], (const float*)d_in[11]};
    float* out = (float*)d_out;

    noise_kernel<<<dim3(28, 10), 256>>>();
    hyp_kernel<<<5, 256>>>(Tpred);

    const int Cs[3]   = {128, 64, 32};
    const int Hs[3]   = {48, 96, 192};
    const int Ws[3]   = {64, 128, 256};
    const int offs[3] = {0, 24576, 122880};
    for (int L = 0; L < 3; L++) {
        dim3 g((Ws[L] + 30) / 31, Hs[L], BATCH);
        size_t sm = (size_t)2 * 32 * (Cs[L] + 4) * sizeof(float);
        gram_kernel<<<g, 256, sm>>>(q[L], r[L], Cs[L], Hs[L], Ws[L], offs[L]);
    }

    const int   nIt[3]  = {2, 3, 4};
    const float damp[3] = {0.001f, 0.0005f, 0.00025f};
    const float scl[3]  = {0.25f, 0.5f, 1.0f};
    int it = 0;
    for (int L = 0; L < 3; L++)
        for (int k = 0; k < nIt[L]; k++, it++)
            iter_kernel<<<BATCH * 16, 256>>>(geo, Kin, u[L],
                                             Hs[L], Ws[L], offs[L], scl[L],
                                             it, damp[L]);

    final_kernel<<<BATCH, 160>>>(Tpred, out);
}

// round 9
// speedup vs baseline: 1.1760x; 1.1760x over previous
#include <cuda_runtime.h>
#include <cuda_bf16.h>
#include <math.h>
#include <stdint.h>

#define BATCH 8
#define NPTS  500
#define MHYP  144

// table offsets (floats): L0: 8*48*64=24576 ; L1: +8*96*128 -> 122880 ; total +8*192*256
#define TAB_TOTAL 516096

__device__ float g_tabS [TAB_TOTAL];
__device__ float g_tabCh[TAB_TOTAL];
__device__ float g_tabCv[TAB_TOTAL];
__device__ float g_tabCd[TAB_TOTAL];
__device__ float g_tabCa[TAB_TOTAL];
__device__ float g_Tcur [BATCH * MHYP * 16];
__device__ float g_costs[BATCH * MHYP];

// ---------------- JAX threefry2x32 (bit-exact) ----------------
__device__ __forceinline__ void threefry2x32(uint32_t k0, uint32_t k1,
                                             uint32_t c0, uint32_t c1,
                                             uint32_t& o0, uint32_t& o1)
{
    uint32_t ks0 = k0, ks1 = k1, ks2 = k0 ^ k1 ^ 0x1BD11BDAu;
    uint32_t x0 = c0 + ks0;
    uint32_t x1 = c1 + ks1;
#define TF_ROT(v,d) (((v) << (d)) | ((v) >> (32 - (d))))
#define TF_R(r) { x0 += x1; x1 = TF_ROT(x1, r); x1 ^= x0; }
    TF_R(13) TF_R(15) TF_R(26) TF_R(6)   x0 += ks1; x1 += ks2 + 1u;
    TF_R(17) TF_R(29) TF_R(16) TF_R(24)  x0 += ks2; x1 += ks0 + 2u;
    TF_R(13) TF_R(15) TF_R(26) TF_R(6)   x0 += ks0; x1 += ks1 + 3u;
    TF_R(17) TF_R(29) TF_R(16) TF_R(24)  x0 += ks1; x1 += ks2 + 4u;
    TF_R(13) TF_R(15) TF_R(26) TF_R(6)   x0 += ks2; x1 += ks0 + 5u;
#undef TF_R
#undef TF_ROT
    o0 = x0; o1 = x1;
}

// Partitionable threefry random_bits (modern JAX default):
// element i -> counter (0, i), 32-bit output = o0 ^ o1.
__device__ __forceinline__ uint32_t tf_bits_partitionable(uint32_t k0, uint32_t k1,
                                                          uint32_t i)
{
    uint32_t o0, o1;
    threefry2x32(k0, k1, 0u, i, o0, o1);
    return o0 ^ o1;
}

__device__ __forceinline__ float bits_to_normal(uint32_t bits)
{
    float f  = __uint_as_float((bits >> 9) | 0x3F800000u) - 1.0f;
    float lo = __uint_as_float(0xBF7FFFFFu); // nextafter(-1, 0)
    float u  = fmaxf(lo, f * 2.0f + lo);     // (hi-lo) rounds to 2.0f; f*2 exact
    return 1.41421356237309515f * erfinvf(u);
}

// ---------------- SE(3) helpers ----------------
__device__ __forceinline__ void se3_exp(const float xi[6], float T[16])
{
    float wx = xi[3], wy = xi[4], wz = xi[5];
    float nw = sqrtf(wx*wx + wy*wy + wz*wz);
    float theta = fmaxf(nw, 1e-8f);
    float inv = 1.0f / theta;
    float ux = wx * inv, uy = wy * inv, uz = wz * inv;
    float K[9] = {0.f, -uz, uy,  uz, 0.f, -ux,  -uy, ux, 0.f};
    float KK[9];
#pragma unroll
    for (int r = 0; r < 3; r++)
#pragma unroll
        for (int c = 0; c < 3; c++)
            KK[r*3+c] = K[r*3+0]*K[0*3+c] + K[r*3+1]*K[1*3+c] + K[r*3+2]*K[2*3+c];
    float st = sinf(theta);
    float ct = 1.0f - cosf(theta);
    float cth = ct * inv;
    float sth = 1.0f - st * inv;
    float R[9], V[9];
#pragma unroll
    for (int k = 0; k < 9; k++) {
        float eye = (k == 0 || k == 4 || k == 8) ? 1.0f : 0.0f;
        R[k] = eye + st  * K[k] + ct  * KK[k];
        V[k] = eye + cth * K[k] + sth * KK[k];
    }
    float t0 = V[0]*xi[0] + V[1]*xi[1] + V[2]*xi[2];
    float t1 = V[3]*xi[0] + V[4]*xi[1] + V[5]*xi[2];
    float t2 = V[6]*xi[0] + V[7]*xi[1] + V[8]*xi[2];
    T[0]=R[0]; T[1]=R[1]; T[2]=R[2];  T[3]=t0;
    T[4]=R[3]; T[5]=R[4]; T[6]=R[5];  T[7]=t1;
    T[8]=R[6]; T[9]=R[7]; T[10]=R[8]; T[11]=t2;
    T[12]=0.f; T[13]=0.f; T[14]=0.f;  T[15]=1.f;
}

__device__ __forceinline__ void mat4_mul(const float* A, const float* B, float* C)
{
#pragma unroll
    for (int r = 0; r < 4; r++)
#pragma unroll
        for (int c = 0; c < 4; c++)
            C[r*4+c] = A[r*4+0]*B[0*4+c] + A[r*4+1]*B[1*4+c]
                     + A[r*4+2]*B[2*4+c] + A[r*4+3]*B[3*4+c];
}

__device__ __forceinline__ float geod_norm(const float T[16])
{
    float tr = T[0] + T[5] + T[10];
    float ca = (tr - 1.0f) * 0.5f;
    ca = fminf(fmaxf(ca, -1.0f + 1e-7f), 1.0f - 1e-7f);
    float theta = acosf(ca);
    float th = fmaxf(theta, 1e-8f);
    float s  = fmaxf(sinf(th), 1e-8f);
    float k  = th / (2.0f * s);
    float wx = (T[9] - T[6]) * k;
    float wy = (T[2] - T[8]) * k;
    float wz = (T[4] - T[1]) * k;
    if (fabsf(theta) < 1e-6f) { wx = 0.f; wy = 0.f; wz = 0.f; }
    float tx = T[3], ty = T[7], tz = T[11];
    return sqrtf(tx*tx + ty*ty + tz*tz + wx*wx + wy*wy + wz*wz);
}

// ---------------- Kernel 1: hypotheses + cost init (PRNG inline) ----------------
__global__ void init_hyp(const float* __restrict__ Tpred)
{
    int t = blockIdx.x * blockDim.x + threadIdx.x;
    if (t >= BATCH * MHYP) return;
    int b = t / MHYP, m = t - b * MHYP;
    g_costs[t] = 0.0f;

    uint32_t hk0, hk1;
    threefry2x32(0u, 42u, 0u, 0u, hk0, hk1);     // fold_in(key(42), 0)
    float n0 = bits_to_normal(tf_bits_partitionable(hk0, hk1, (uint32_t)(m*3+0)));
    float n1 = bits_to_normal(tf_bits_partitionable(hk0, hk1, (uint32_t)(m*3+1)));
    float n2 = bits_to_normal(tf_bits_partitionable(hk0, hk1, (uint32_t)(m*3+2)));

    const float D2R = 0.017453292519943295f;
    float pitch = (-11.0f + 2.0f * (float)(m / 12)) * D2R;
    float yaw   = (-11.0f + 2.0f * (float)(m % 12)) * D2R;
    float xi[6] = { n0, n1, n2, 0.0f, pitch, yaw };
    float dT[16]; se3_exp(xi, dT);
    float Tn[16]; mat4_mul(dT, Tpred + b * 16, Tn);
#pragma unroll
    for (int k = 0; k < 16; k++) g_Tcur[t * 16 + k] = Tn[k];
}

// ---------------- Kernel 2: fused neighbor Gram tables (all 3 levels) ----------------
// Thread owns 4 consecutive x (float4). Per channel: load q/r rows y & y+1,
// diff, get neighbor via shfl_down (clamped at row end; scalar load at
// mid-row warp boundary), accumulate 5 dot tables in registers.
// Threads: L0 8*48*16=6144 | L1 8*96*32=24576 | L2 8*192*64=98304  -> 129024 = 504*256
__global__ __launch_bounds__(256)
void gram_all(const float* __restrict__ q0, const float* __restrict__ q1,
              const float* __restrict__ q2,
              const float* __restrict__ r0, const float* __restrict__ r1,
              const float* __restrict__ r2)
{
    int t = blockIdx.x * 256 + threadIdx.x;
    int L, base;
    if (t < 6144)       { L = 0; base = 0; }
    else if (t < 30720) { L = 1; base = 6144; }
    else                { L = 2; base = 30720; }

    const int Cs[3] = {128, 64, 32};
    const int Hs[3] = {48, 96, 192};
    const int Ws[3] = {64, 128, 256};
    const int Os[3] = {0, 24576, 122880};
    const int C = Cs[L], H = Hs[L], W = Ws[L];
    const float* __restrict__ qp = (L == 0) ? q0 : ((L == 1) ? q1 : q2);
    const float* __restrict__ rp = (L == 0) ? r0 : ((L == 1) ? r1 : r2);

    int tt = t - base;
    int W4 = W >> 2;
    int x4 = tt % W4;
    int rest = tt / W4;
    int y = rest % H;
    int b = rest / H;
    int yd = min(y + 1, H - 1);
    int x = x4 << 2;
    int lane = threadIdx.x & 31;
    bool rowend = (x4 == W4 - 1);
    bool need_scalar = (!rowend) && (lane == 31);

    const int chs = H * W;
    int base_y = (b * C * H + y)  * W + x;
    int base_d = (b * C * H + yd) * W + x;
    const float* qy = qp + base_y;
    const float* ry = rp + base_y;
    const float* qd = qp + base_d;
    const float* rd = rp + base_d;

    float vS0=0,vS1=0,vS2=0,vS3=0;
    float vH0=0,vH1=0,vH2=0,vH3=0;
    float vV0=0,vV1=0,vV2=0,vV3=0;
    float vD0=0,vD1=0,vD2=0,vD3=0;
    float vA0=0,vA1=0,vA2=0,vA3=0;

    for (int c = 0; c < C; c++) {
        float4 qa = *(const float4*)qy;
        float4 ra = *(const float4*)ry;
        float4 qc = *(const float4*)qd;
        float4 rc = *(const float4*)rd;
        float a0 = qa.x - ra.x, a1 = qa.y - ra.y, a2 = qa.z - ra.z, a3 = qa.w - ra.w;
        float c0 = qc.x - rc.x, c1 = qc.y - rc.y, c2 = qc.z - rc.z, c3 = qc.w - rc.w;
        float an = __shfl_down_sync(0xFFFFFFFFu, a0, 1);
        float cn = __shfl_down_sync(0xFFFFFFFFu, c0, 1);
        if (need_scalar) { an = qy[4] - ry[4]; cn = qd[4] - rd[4]; }
        if (rowend)      { an = a3; cn = c3; }

        vS0 += a0*a0; vS1 += a1*a1; vS2 += a2*a2; vS3 += a3*a3;
        vH0 += a0*a1; vH1 += a1*a2; vH2 += a2*a3; vH3 += a3*an;
        vV0 += a0*c0; vV1 += a1*c1; vV2 += a2*c2; vV3 += a3*c3;
        vD0 += a0*c1; vD1 += a1*c2; vD2 += a2*c3; vD3 += a3*cn;
        vA0 += a1*c0; vA1 += a2*c1; vA2 += a3*c2; vA3 += an*c3;

        qy += chs; ry += chs; qd += chs; rd += chs;
    }

    int o = Os[L] + (b * H + y) * W + x;
    *(float4*)&g_tabS [o] = make_float4(vS0, vS1, vS2, vS3);
    *(float4*)&g_tabCh[o] = make_float4(vH0, vH1, vH2, vH3);
    *(float4*)&g_tabCv[o] = make_float4(vV0, vV1, vV2, vV3);
    *(float4*)&g_tabCd[o] = make_float4(vD0, vD1, vD2, vD3);
    *(float4*)&g_tabCa[o] = make_float4(vA0, vA1, vA2, vA3);
}

// ---------------- Kernel 3: fused 9 LM iterations ----------------
// block = (b*16 + m); per-(b,m) chains are independent -> block-local sync only.
__global__ __launch_bounds__(256)
void fused_iter(const float* __restrict__ geo,
                const float* __restrict__ Kin,
                const float* __restrict__ u0,
                const float* __restrict__ u1,
                const float* __restrict__ u2)
{
    const int b = blockIdx.x >> 4;
    const int m = blockIdx.x & 15;
    const int tid = threadIdx.x;

    __shared__ float sT[16];
    __shared__ float sgeo[NPTS * 3];
    __shared__ float sxi[6];
    __shared__ float sred[8];

    if (tid < 16) sT[tid] = g_Tcur[(b * MHYP + m) * 16 + tid];
    for (int i = tid; i < NPTS * 3; i += 256) sgeo[i] = geo[b * NPTS * 3 + i];
    __syncthreads();

    const int   itH[9]    = {48,48, 96,96,96, 192,192,192,192};
    const int   itW[9]    = {64,64, 128,128,128, 256,256,256,256};
    const int   itOff[9]  = {0,0, 24576,24576,24576, 122880,122880,122880,122880};
    const float itScl[9]  = {0.25f,0.25f, 0.5f,0.5f,0.5f, 1.0f,1.0f,1.0f,1.0f};
    const float itDmp[9]  = {0.001f,0.001f, 0.0005f,0.0005f,0.0005f,
                             0.00025f,0.00025f,0.00025f,0.00025f};
    const uint32_t itDat[9] = {100u,101u, 110u,111u,112u, 120u,121u,122u,123u};

    const float fxK = Kin[b*9+0], cxK = Kin[b*9+2];
    const float fyK = Kin[b*9+4], cyK = Kin[b*9+5];

    for (int it = 0; it < 9; it++) {
        // 6 noise draws for this (b,m,it) — computed by 6 lanes, used by tid0 after sync
        if (tid < 6) {
            uint32_t hk0, hk1;
            threefry2x32(0u, 42u, 0u, itDat[it], hk0, hk1);
            uint32_t i = (uint32_t)((b * MHYP + m) * 6 + tid);
            sxi[tid] = bits_to_normal(tf_bits_partitionable(hk0, hk1, i));
        }

        const int H = itH[it], W = itW[it];
        const float scale = itScl[it];
        const float fx = fxK * scale, cx = cxK * scale;
        const float fy = fyK * scale, cy = cyK * scale;
        const float* U = ((it < 2) ? u0 : ((it < 5) ? u1 : u2)) + b * H * W;
        const int tb = itOff[it] + b * H * W;
        const float Wm1 = (float)(W - 1), Hm1 = (float)(H - 1);
        const float Wf = (float)W, Hf = (float)H;

        float local = 0.0f;
        for (int n = tid; n < NPTS; n += 256) {
            float X = sgeo[n*3 + 0];
            float Y = sgeo[n*3 + 1];
            float Z = sgeo[n*3 + 2];
            float pc0 = sT[0]*X + sT[1]*Y + sT[2]*Z  + sT[3];
            float pc1 = sT[4]*X + sT[5]*Y + sT[6]*Z  + sT[7];
            float pc2 = sT[8]*X + sT[9]*Y + sT[10]*Z + sT[11];
            float z = fmaxf(pc2, 1e-6f);
            float uu = fx * (pc0 / z) + cx;
            float vv = fy * (pc1 / z) + cy;
            float gx = 2.0f * uu / Wm1 - 1.0f;
            float gy = 2.0f * vv / Hm1 - 1.0f;
            float xx = fminf(fmaxf(((gx + 1.0f) * Wf - 1.0f) * 0.5f, 0.0f), Wm1);
            float yy = fminf(fmaxf(((gy + 1.0f) * Hf - 1.0f) * 0.5f, 0.0f), Hm1);
            float x0f = floorf(xx), y0f = floorf(yy);
            float wx = xx - x0f, wy = yy - y0f;
            int x0 = (int)x0f, y0 = (int)y0f;
            int x1 = min(x0 + 1, W - 1), y1 = min(y0 + 1, H - 1);
            float ox = 1.0f - wx, oy = 1.0f - wy;
            float w00 = ox*oy, wX0 = wx*oy, w0Y = ox*wy, wXY = wx*wy;
            int i00 = tb + y0*W + x0;
            int i10 = tb + y0*W + x1;
            int i01 = tb + y1*W + x0;
            int i11 = tb + y1*W + x1;
            float S00 = __ldg(&g_tabS[i00]);
            float S10 = __ldg(&g_tabS[i10]);
            float S01 = __ldg(&g_tabS[i01]);
            float S11 = __ldg(&g_tabS[i11]);
            float ChA = __ldg(&g_tabCh[i00]);
            float ChB = __ldg(&g_tabCh[i01]);
            float CvA = __ldg(&g_tabCv[i00]);
            float CvB = __ldg(&g_tabCv[i10]);
            float CdA = __ldg(&g_tabCd[i00]);
            float CaA = __ldg(&g_tabCa[i00]);
            float quad = w00*w00*S00 + wX0*wX0*S10 + w0Y*w0Y*S01 + wXY*wXY*S11
                       + 2.0f*(w00*wX0*ChA + w0Y*wXY*ChB + w00*w0Y*CvA
                             + wX0*wXY*CvB + w00*wXY*CdA + wX0*w0Y*CaA);
            float us = __ldg(&U[y0*W + x0]) * w00 + __ldg(&U[y0*W + x1]) * wX0
                     + __ldg(&U[y1*W + x0]) * w0Y + __ldg(&U[y1*W + x1]) * wXY;
            local += quad * us;
        }
#pragma unroll
        for (int off = 16; off > 0; off >>= 1)
            local += __shfl_xor_sync(0xFFFFFFFFu, local, off);
        if ((tid & 31) == 0) sred[tid >> 5] = local;
        __syncthreads();
        if (tid == 0) {
            float s = 0.0f;
#pragma unroll
            for (int w = 0; w < 8; w++) s += sred[w];
            float res = s / (float)NPTS;
            g_costs[b * MHYP + m] = res;
            float a1 = -itDmp[it] * res;
            float xi[6];
#pragma unroll
            for (int k = 0; k < 6; k++) xi[k] = a1 * sxi[k] * 0.01f;
            float dT[16]; se3_exp(xi, dT);
            float Told[16];
#pragma unroll
            for (int k = 0; k < 16; k++) Told[k] = sT[k];
            float Tn[16]; mat4_mul(dT, Told, Tn);
#pragma unroll
            for (int k = 0; k < 16; k++) sT[k] = Tn[k];
        }
        __syncthreads();
    }

    if (tid < 16) g_Tcur[(b * MHYP + m) * 16 + tid] = sT[tid];
}

// ---------------- Kernel 4: finalize (geodesic + argmin + outputs) ----------------
__global__ void final_kernel(const float* __restrict__ Tpred, float* __restrict__ out)
{
    int b = blockIdx.x;
    int t = threadIdx.x; // 160 threads
    __shared__ float sInv[16];
    __shared__ float sTot[MHYP];
    __shared__ int sBest;
    if (t == 0) {
        const float* Tp = Tpred + b * 16;
        sInv[0]=Tp[0]; sInv[1]=Tp[4]; sInv[2] =Tp[8];
        sInv[4]=Tp[1]; sInv[5]=Tp[5]; sInv[6] =Tp[9];
        sInv[8]=Tp[2]; sInv[9]=Tp[6]; sInv[10]=Tp[10];
        sInv[3]  = -(Tp[0]*Tp[3] + Tp[4]*Tp[7] + Tp[8]*Tp[11]);
        sInv[7]  = -(Tp[1]*Tp[3] + Tp[5]*Tp[7] + Tp[9]*Tp[11]);
        sInv[11] = -(Tp[2]*Tp[3] + Tp[6]*Tp[7] + Tp[10]*Tp[11]);
        sInv[12]=0.f; sInv[13]=0.f; sInv[14]=0.f; sInv[15]=1.f;
    }
    __syncthreads();
    if (t < MHYP) {
        float Trel[16];
        mat4_mul(&g_Tcur[(b * MHYP + t) * 16], sInv, Trel);
        float c = g_costs[b * MHYP + t];
        sTot[t] = c + geod_norm(Trel);
        out[BATCH * 16 + b * MHYP + t] = c;
    }
    __syncthreads();
    if (t == 0) {
        float best = sTot[0]; int bi = 0;
        for (int mm = 1; mm < MHYP; mm++)
            if (sTot[mm] < best) { best = sTot[mm]; bi = mm; }
        sBest = bi;
    }
    __syncthreads();
    if (t < 16) out[b * 16 + t] = g_Tcur[(b * MHYP + sBest) * 16 + t];
}

// ---------------- launch ----------------
extern "C" void kernel_launch(void* const* d_in, const int* in_sizes, int n_in,
                              void* d_out, int out_size)
{
    const float* Tpred = (const float*)d_in[0];
    const float* geo   = (const float*)d_in[1];
    const float* Kin   = (const float*)d_in[2];
    const float* q0 = (const float*)d_in[3];
    const float* q1 = (const float*)d_in[4];
    const float* q2 = (const float*)d_in[5];
    const float* r0 = (const float*)d_in[6];
    const float* r1 = (const float*)d_in[7];
    const float* r2 = (const float*)d_in[8];
    const float* u0 = (const float*)d_in[9];
    const float* u1 = (const float*)d_in[10];
    const float* u2 = (const float*)d_in[11];
    float* out = (float*)d_out;

    init_hyp<<<5, 256>>>(Tpred);
    gram_all<<<504, 256>>>(q0, q1, q2, r0, r1, r2);
    fused_iter<<<BATCH * 16, 256>>>(geo, Kin, u0, u1, u2);
    final_kernel<<<BATCH, 160>>>(Tpred, out);
}

// round 10
// speedup vs baseline: 1.4918x; 1.2685x over previous
#include <cuda_runtime.h>
#include <cuda_bf16.h>
#include <math.h>
#include <stdint.h>

#define BATCH 8
#define NPTS  500
#define MHYP  144

// table offsets (floats): L0: 8*48*64=24576 ; L1: +8*96*128 -> 122880 ; total +8*192*256
#define TAB_TOTAL 516096

__device__ float g_tabS [TAB_TOTAL];
__device__ float g_tabCh[TAB_TOTAL];
__device__ float g_tabCv[TAB_TOTAL];
__device__ float g_tabCd[TAB_TOTAL];
__device__ float g_tabCa[TAB_TOTAL];
__device__ float g_Tcur [BATCH * MHYP * 16];
__device__ float g_costs[BATCH * MHYP];

// ---------------- JAX threefry2x32 (bit-exact) ----------------
__device__ __forceinline__ void threefry2x32(uint32_t k0, uint32_t k1,
                                             uint32_t c0, uint32_t c1,
                                             uint32_t& o0, uint32_t& o1)
{
    uint32_t ks0 = k0, ks1 = k1, ks2 = k0 ^ k1 ^ 0x1BD11BDAu;
    uint32_t x0 = c0 + ks0;
    uint32_t x1 = c1 + ks1;
#define TF_ROT(v,d) (((v) << (d)) | ((v) >> (32 - (d))))
#define TF_R(r) { x0 += x1; x1 = TF_ROT(x1, r); x1 ^= x0; }
    TF_R(13) TF_R(15) TF_R(26) TF_R(6)   x0 += ks1; x1 += ks2 + 1u;
    TF_R(17) TF_R(29) TF_R(16) TF_R(24)  x0 += ks2; x1 += ks0 + 2u;
    TF_R(13) TF_R(15) TF_R(26) TF_R(6)   x0 += ks0; x1 += ks1 + 3u;
    TF_R(17) TF_R(29) TF_R(16) TF_R(24)  x0 += ks1; x1 += ks2 + 4u;
    TF_R(13) TF_R(15) TF_R(26) TF_R(6)   x0 += ks2; x1 += ks0 + 5u;
#undef TF_R
#undef TF_ROT
    o0 = x0; o1 = x1;
}

__device__ __forceinline__ uint32_t tf_bits_partitionable(uint32_t k0, uint32_t k1,
                                                          uint32_t i)
{
    uint32_t o0, o1;
    threefry2x32(k0, k1, 0u, i, o0, o1);
    return o0 ^ o1;
}

__device__ __forceinline__ float bits_to_normal(uint32_t bits)
{
    float f  = __uint_as_float((bits >> 9) | 0x3F800000u) - 1.0f;
    float lo = __uint_as_float(0xBF7FFFFFu); // nextafter(-1, 0)
    float u  = fmaxf(lo, f * 2.0f + lo);
    return 1.41421356237309515f * erfinvf(u);
}

// ---------------- SE(3) helpers ----------------
__device__ __forceinline__ void se3_exp(const float xi[6], float T[16])
{
    float wx = xi[3], wy = xi[4], wz = xi[5];
    float nw = sqrtf(wx*wx + wy*wy + wz*wz);
    float theta = fmaxf(nw, 1e-8f);
    float inv = 1.0f / theta;
    float ux = wx * inv, uy = wy * inv, uz = wz * inv;
    float K[9] = {0.f, -uz, uy,  uz, 0.f, -ux,  -uy, ux, 0.f};
    float KK[9];
#pragma unroll
    for (int r = 0; r < 3; r++)
#pragma unroll
        for (int c = 0; c < 3; c++)
            KK[r*3+c] = K[r*3+0]*K[0*3+c] + K[r*3+1]*K[1*3+c] + K[r*3+2]*K[2*3+c];
    float st = sinf(theta);
    float ct = 1.0f - cosf(theta);
    float cth = ct * inv;
    float sth = 1.0f - st * inv;
    float R[9], V[9];
#pragma unroll
    for (int k = 0; k < 9; k++) {
        float eye = (k == 0 || k == 4 || k == 8) ? 1.0f : 0.0f;
        R[k] = eye + st  * K[k] + ct  * KK[k];
        V[k] = eye + cth * K[k] + sth * KK[k];
    }
    float t0 = V[0]*xi[0] + V[1]*xi[1] + V[2]*xi[2];
    float t1 = V[3]*xi[0] + V[4]*xi[1] + V[5]*xi[2];
    float t2 = V[6]*xi[0] + V[7]*xi[1] + V[8]*xi[2];
    T[0]=R[0]; T[1]=R[1]; T[2]=R[2];  T[3]=t0;
    T[4]=R[3]; T[5]=R[4]; T[6]=R[5];  T[7]=t1;
    T[8]=R[6]; T[9]=R[7]; T[10]=R[8]; T[11]=t2;
    T[12]=0.f; T[13]=0.f; T[14]=0.f;  T[15]=1.f;
}

__device__ __forceinline__ void mat4_mul(const float* A, const float* B, float* C)
{
#pragma unroll
    for (int r = 0; r < 4; r++)
#pragma unroll
        for (int c = 0; c < 4; c++)
            C[r*4+c] = A[r*4+0]*B[0*4+c] + A[r*4+1]*B[1*4+c]
                     + A[r*4+2]*B[2*4+c] + A[r*4+3]*B[3*4+c];
}

__device__ __forceinline__ float geod_norm(const float T[16])
{
    float tr = T[0] + T[5] + T[10];
    float ca = (tr - 1.0f) * 0.5f;
    ca = fminf(fmaxf(ca, -1.0f + 1e-7f), 1.0f - 1e-7f);
    float theta = acosf(ca);
    float th = fmaxf(theta, 1e-8f);
    float s  = fmaxf(sinf(th), 1e-8f);
    float k  = th / (2.0f * s);
    float wx = (T[9] - T[6]) * k;
    float wy = (T[2] - T[8]) * k;
    float wz = (T[4] - T[1]) * k;
    if (fabsf(theta) < 1e-6f) { wx = 0.f; wy = 0.f; wz = 0.f; }
    float tx = T[3], ty = T[7], tz = T[11];
    return sqrtf(tx*tx + ty*ty + tz*tz + wx*wx + wy*wy + wz*wz);
}

// ---------------- Kernel 1: hypotheses + cost init (PRNG inline) ----------------
__global__ void init_hyp(const float* __restrict__ Tpred)
{
    int t = blockIdx.x * blockDim.x + threadIdx.x;
    if (t >= BATCH * MHYP) return;
    int b = t / MHYP, m = t - b * MHYP;
    g_costs[t] = 0.0f;

    uint32_t hk0, hk1;
    threefry2x32(0u, 42u, 0u, 0u, hk0, hk1);     // fold_in(key(42), 0)
    float n0 = bits_to_normal(tf_bits_partitionable(hk0, hk1, (uint32_t)(m*3+0)));
    float n1 = bits_to_normal(tf_bits_partitionable(hk0, hk1, (uint32_t)(m*3+1)));
    float n2 = bits_to_normal(tf_bits_partitionable(hk0, hk1, (uint32_t)(m*3+2)));

    const float D2R = 0.017453292519943295f;
    float pitch = (-11.0f + 2.0f * (float)(m / 12)) * D2R;
    float yaw   = (-11.0f + 2.0f * (float)(m % 12)) * D2R;
    float xi[6] = { n0, n1, n2, 0.0f, pitch, yaw };
    float dT[16]; se3_exp(xi, dT);
    float Tn[16]; mat4_mul(dT, Tpred + b * 16, Tn);
#pragma unroll
    for (int k = 0; k < 16; k++) g_Tcur[t * 16 + k] = Tn[k];
}

// ---------------- Kernel 2: balanced fused neighbor Gram tables ----------------
// Every thread does exactly 32 channel-iterations. Channel dim is split into
// groups (L0: 4 groups, L1: 2, L2: 1); block-local smem reduction combines
// groups. Grid: 96 (L0) + 192 (L1) + 384 (L2) = 672 blocks x 256 threads.
#define GPITCH 21
__global__ __launch_bounds__(256)
void gram_all(const float* __restrict__ q0, const float* __restrict__ q1,
              const float* __restrict__ q2,
              const float* __restrict__ r0, const float* __restrict__ r1,
              const float* __restrict__ r2)
{
    __shared__ float sbuf[256 * GPITCH];   // 21.5 KB
    const int blk = blockIdx.x;
    const int tid = threadIdx.x;

    int L, qbase, nOut, gshift, lgW4, H, W, C, Off;
    const float* __restrict__ qp;
    const float* __restrict__ rp;
    if (blk < 96)       { L = 0; qbase = blk * 64;          nOut = 64;  gshift = 6; lgW4 = 4; H = 48;  W = 64;  C = 128; Off = 0;      qp = q0; rp = r0; }
    else if (blk < 288) { L = 1; qbase = (blk - 96) * 128;  nOut = 128; gshift = 7; lgW4 = 5; H = 96;  W = 128; C = 64;  Off = 24576;  qp = q1; rp = r1; }
    else                { L = 2; qbase = (blk - 288) * 256; nOut = 256; gshift = 8; lgW4 = 6; H = 192; W = 256; C = 32;  Off = 122880; qp = q2; rp = r2; }

    const int p    = tid & (nOut - 1);
    const int g    = tid >> gshift;
    const int quad = qbase + p;
    const int W4   = 1 << lgW4;
    const int x4   = quad & (W4 - 1);
    const int y    = (quad >> lgW4) % H;
    const int b    = (quad >> lgW4) / H;
    const int yd   = min(y + 1, H - 1);
    const int x    = x4 << 2;
    const int lane = tid & 31;
    const bool rowend      = (x4 == W4 - 1);
    const bool need_scalar = (!rowend) && (lane == 31);

    const int chs = H * W;
    const int c0c = g * 32;
    const float* qy = qp + ((b * C + c0c) * H + y)  * W + x;
    const float* ry = rp + ((b * C + c0c) * H + y)  * W + x;
    const float* qd = qp + ((b * C + c0c) * H + yd) * W + x;
    const float* rd = rp + ((b * C + c0c) * H + yd) * W + x;

    float vS0=0,vS1=0,vS2=0,vS3=0;
    float vH0=0,vH1=0,vH2=0,vH3=0;
    float vV0=0,vV1=0,vV2=0,vV3=0;
    float vD0=0,vD1=0,vD2=0,vD3=0;
    float vA0=0,vA1=0,vA2=0,vA3=0;

#pragma unroll 4
    for (int c = 0; c < 32; c++) {
        float4 qa = *(const float4*)qy;
        float4 ra = *(const float4*)ry;
        float4 qc = *(const float4*)qd;
        float4 rc = *(const float4*)rd;
        float a0 = qa.x - ra.x, a1 = qa.y - ra.y, a2 = qa.z - ra.z, a3 = qa.w - ra.w;
        float c0 = qc.x - rc.x, c1 = qc.y - rc.y, c2 = qc.z - rc.z, c3 = qc.w - rc.w;
        float an = __shfl_down_sync(0xFFFFFFFFu, a0, 1);
        float cn = __shfl_down_sync(0xFFFFFFFFu, c0, 1);
        if (need_scalar) { an = qy[4] - ry[4]; cn = qd[4] - rd[4]; }
        if (rowend)      { an = a3; cn = c3; }

        vS0 += a0*a0; vS1 += a1*a1; vS2 += a2*a2; vS3 += a3*a3;
        vH0 += a0*a1; vH1 += a1*a2; vH2 += a2*a3; vH3 += a3*an;
        vV0 += a0*c0; vV1 += a1*c1; vV2 += a2*c2; vV3 += a3*c3;
        vD0 += a0*c1; vD1 += a1*c2; vD2 += a2*c3; vD3 += a3*cn;
        vA0 += a1*c0; vA1 += a2*c1; vA2 += a3*c2; vA3 += an*c3;

        qy += chs; ry += chs; qd += chs; rd += chs;
    }

    float* sp = &sbuf[tid * GPITCH];
    sp[0]=vS0; sp[1]=vS1; sp[2]=vS2; sp[3]=vS3;
    sp[4]=vH0; sp[5]=vH1; sp[6]=vH2; sp[7]=vH3;
    sp[8]=vV0; sp[9]=vV1; sp[10]=vV2; sp[11]=vV3;
    sp[12]=vD0; sp[13]=vD1; sp[14]=vD2; sp[15]=vD3;
    sp[16]=vA0; sp[17]=vA1; sp[18]=vA2; sp[19]=vA3;
    __syncthreads();

    if (tid < nOut) {
        float acc[20];
        const float* s0 = &sbuf[tid * GPITCH];
#pragma unroll
        for (int k = 0; k < 20; k++) acc[k] = s0[k];
        for (int gg = 1; gg < (256 / nOut); gg++) {
            const float* sg = &sbuf[(gg * nOut + tid) * GPITCH];
#pragma unroll
            for (int k = 0; k < 20; k++) acc[k] += sg[k];
        }
        int o = Off + (b * H + y) * W + x;
        *(float4*)&g_tabS [o] = make_float4(acc[0],  acc[1],  acc[2],  acc[3]);
        *(float4*)&g_tabCh[o] = make_float4(acc[4],  acc[5],  acc[6],  acc[7]);
        *(float4*)&g_tabCv[o] = make_float4(acc[8],  acc[9],  acc[10], acc[11]);
        *(float4*)&g_tabCd[o] = make_float4(acc[12], acc[13], acc[14], acc[15]);
        *(float4*)&g_tabCa[o] = make_float4(acc[16], acc[17], acc[18], acc[19]);
    }
}

// ---------------- Kernel 3: fused 9 LM iterations ----------------
// block = (b*16 + m). Pose update computed redundantly by ALL threads
// (no serial tid-0 tail); tid<16 commit sT.
__global__ __launch_bounds__(256)
void fused_iter(const float* __restrict__ geo,
                const float* __restrict__ Kin,
                const float* __restrict__ u0,
                const float* __restrict__ u1,
                const float* __restrict__ u2)
{
    const int b = blockIdx.x >> 4;
    const int m = blockIdx.x & 15;
    const int tid = threadIdx.x;

    __shared__ float sT[16];
    __shared__ float sgeo[NPTS * 3];
    __shared__ float sxi[6];
    __shared__ float sred[8];

    if (tid < 16) sT[tid] = g_Tcur[(b * MHYP + m) * 16 + tid];
    for (int i = tid; i < NPTS * 3; i += 256) sgeo[i] = geo[b * NPTS * 3 + i];
    __syncthreads();

    const int   itH[9]    = {48,48, 96,96,96, 192,192,192,192};
    const int   itW[9]    = {64,64, 128,128,128, 256,256,256,256};
    const int   itOff[9]  = {0,0, 24576,24576,24576, 122880,122880,122880,122880};
    const float itScl[9]  = {0.25f,0.25f, 0.5f,0.5f,0.5f, 1.0f,1.0f,1.0f,1.0f};
    const float itDmp[9]  = {0.001f,0.001f, 0.0005f,0.0005f,0.0005f,
                             0.00025f,0.00025f,0.00025f,0.00025f};
    const uint32_t itDat[9] = {100u,101u, 110u,111u,112u, 120u,121u,122u,123u};

    const float fxK = Kin[b*9+0], cxK = Kin[b*9+2];
    const float fyK = Kin[b*9+4], cyK = Kin[b*9+5];

    for (int it = 0; it < 9; it++) {
        if (tid < 6) {
            uint32_t hk0, hk1;
            threefry2x32(0u, 42u, 0u, itDat[it], hk0, hk1);
            uint32_t i = (uint32_t)((b * MHYP + m) * 6 + tid);
            sxi[tid] = bits_to_normal(tf_bits_partitionable(hk0, hk1, i));
        }

        const int H = itH[it], W = itW[it];
        const float scale = itScl[it];
        const float fx = fxK * scale, cx = cxK * scale;
        const float fy = fyK * scale, cy = cyK * scale;
        const float* U = ((it < 2) ? u0 : ((it < 5) ? u1 : u2)) + b * H * W;
        const int tb = itOff[it] + b * H * W;
        const float Wm1 = (float)(W - 1), Hm1 = (float)(H - 1);
        const float Wf = (float)W, Hf = (float)H;

        float local = 0.0f;
        for (int n = tid; n < NPTS; n += 256) {
            float X = sgeo[n*3 + 0];
            float Y = sgeo[n*3 + 1];
            float Z = sgeo[n*3 + 2];
            float pc0 = sT[0]*X + sT[1]*Y + sT[2]*Z  + sT[3];
            float pc1 = sT[4]*X + sT[5]*Y + sT[6]*Z  + sT[7];
            float pc2 = sT[8]*X + sT[9]*Y + sT[10]*Z + sT[11];
            float z = fmaxf(pc2, 1e-6f);
            float uu = fx * (pc0 / z) + cx;
            float vv = fy * (pc1 / z) + cy;
            float gx = 2.0f * uu / Wm1 - 1.0f;
            float gy = 2.0f * vv / Hm1 - 1.0f;
            float xx = fminf(fmaxf(((gx + 1.0f) * Wf - 1.0f) * 0.5f, 0.0f), Wm1);
            float yy = fminf(fmaxf(((gy + 1.0f) * Hf - 1.0f) * 0.5f, 0.0f), Hm1);
            float x0f = floorf(xx), y0f = floorf(yy);
            float wx = xx - x0f, wy = yy - y0f;
            int x0 = (int)x0f, y0 = (int)y0f;
            int x1 = min(x0 + 1, W - 1), y1 = min(y0 + 1, H - 1);
            float ox = 1.0f - wx, oy = 1.0f - wy;
            float w00 = ox*oy, wX0 = wx*oy, w0Y = ox*wy, wXY = wx*wy;
            int i00 = tb + y0*W + x0;
            int i10 = tb + y0*W + x1;
            int i01 = tb + y1*W + x0;
            int i11 = tb + y1*W + x1;
            float S00 = __ldg(&g_tabS[i00]);
            float S10 = __ldg(&g_tabS[i10]);
            float S01 = __ldg(&g_tabS[i01]);
            float S11 = __ldg(&g_tabS[i11]);
            float ChA = __ldg(&g_tabCh[i00]);
            float ChB = __ldg(&g_tabCh[i01]);
            float CvA = __ldg(&g_tabCv[i00]);
            float CvB = __ldg(&g_tabCv[i10]);
            float CdA = __ldg(&g_tabCd[i00]);
            float CaA = __ldg(&g_tabCa[i00]);
            float quad = w00*w00*S00 + wX0*wX0*S10 + w0Y*w0Y*S01 + wXY*wXY*S11
                       + 2.0f*(w00*wX0*ChA + w0Y*wXY*ChB + w00*w0Y*CvA
                             + wX0*wXY*CvB + w00*wXY*CdA + wX0*w0Y*CaA);
            float us = __ldg(&U[y0*W + x0]) * w00 + __ldg(&U[y0*W + x1]) * wX0
                     + __ldg(&U[y1*W + x0]) * w0Y + __ldg(&U[y1*W + x1]) * wXY;
            local += quad * us;
        }
#pragma unroll
        for (int off = 16; off > 0; off >>= 1)
            local += __shfl_xor_sync(0xFFFFFFFFu, local, off);
        if ((tid & 31) == 0) sred[tid >> 5] = local;
        __syncthreads();

        // ALL threads: reduce, then redundant pose update (identical values)
        float s = 0.0f;
#pragma unroll
        for (int w = 0; w < 8; w++) s += sred[w];
        float res = s / (float)NPTS;
        if (tid == 0) g_costs[b * MHYP + m] = res;
        float a1 = -itDmp[it] * res;
        float xi[6];
#pragma unroll
        for (int k = 0; k < 6; k++) xi[k] = a1 * sxi[k] * 0.01f;
        float dT[16]; se3_exp(xi, dT);
        float Told[16];
#pragma unroll
        for (int k = 0; k < 16; k++) Told[k] = sT[k];
        float Tn[16]; mat4_mul(dT, Told, Tn);
        __syncthreads();
        if (tid < 16) sT[tid] = Tn[tid];
        __syncthreads();
    }

    if (tid < 16) g_Tcur[(b * MHYP + m) * 16 + tid] = sT[tid];
}

// ---------------- Kernel 4: finalize (geodesic + argmin + outputs) ----------------
__global__ void final_kernel(const float* __restrict__ Tpred, float* __restrict__ out)
{
    int b = blockIdx.x;
    int t = threadIdx.x; // 160 threads
    __shared__ float sInv[16];
    __shared__ float sTot[MHYP];
    __shared__ int sBest;
    if (t == 0) {
        const float* Tp = Tpred + b * 16;
        sInv[0]=Tp[0]; sInv[1]=Tp[4]; sInv[2] =Tp[8];
        sInv[4]=Tp[1]; sInv[5]=Tp[5]; sInv[6] =Tp[9];
        sInv[8]=Tp[2]; sInv[9]=Tp[6]; sInv[10]=Tp[10];
        sInv[3]  = -(Tp[0]*Tp[3] + Tp[4]*Tp[7] + Tp[8]*Tp[11]);
        sInv[7]  = -(Tp[1]*Tp[3] + Tp[5]*Tp[7] + Tp[9]*Tp[11]);
        sInv[11] = -(Tp[2]*Tp[3] + Tp[6]*Tp[7] + Tp[10]*Tp[11]);
        sInv[12]=0.f; sInv[13]=0.f; sInv[14]=0.f; sInv[15]=1.f;
    }
    __syncthreads();
    if (t < MHYP) {
        float Trel[16];
        mat4_mul(&g_Tcur[(b * MHYP + t) * 16], sInv, Trel);
        float c = g_costs[b * MHYP + t];
        sTot[t] = c + geod_norm(Trel);
        out[BATCH * 16 + b * MHYP + t] = c;
    }
    __syncthreads();
    if (t == 0) {
        float best = sTot[0]; int bi = 0;
        for (int mm = 1; mm < MHYP; mm++)
            if (sTot[mm] < best) { best = sTot[mm]; bi = mm; }
        sBest = bi;
    }
    __syncthreads();
    if (t < 16) out[b * 16 + t] = g_Tcur[(b * MHYP + sBest) * 16 + t];
}

// ---------------- launch ----------------
extern "C" void kernel_launch(void* const* d_in, const int* in_sizes, int n_in,
                              void* d_out, int out_size)
{
    const float* Tpred = (const float*)d_in[0];
    const float* geo   = (const float*)d_in[1];
    const float* Kin   = (const float*)d_in[2];
    const float* q0 = (const float*)d_in[3];
    const float* q1 = (const float*)d_in[4];
    const float* q2 = (const float*)d_in[5];
    const float* r0 = (const float*)d_in[6];
    const float* r1 = (const float*)d_in[7];
    const float* r2 = (const float*)d_in[8];
    const float* u0 = (const float*)d_in[9];
    const float* u1 = (const float*)d_in[10];
    const float* u2 = (const float*)d_in[11];
    float* out = (float*)d_out;

    init_hyp<<<5, 256>>>(Tpred);
    gram_all<<<672, 256>>>(q0, q1, q2, r0, r1, r2);
    fused_iter<<<BATCH * 16, 256>>>(geo, Kin, u0, u1, u2);
    final_kernel<<<BATCH, 160>>>(Tpred, out);
}